// round 7
// baseline (speedup 1.0000x reference)
#include <cuda_runtime.h>
#include <cuda_bf16.h>
#include <cstdint>
#include <cstddef>

#define NROWS   1024
#define MROWS   (NROWS*NROWS)
#define FIN     128
#define FHID    64
#define EPSV    1e-5f
#define ALPHAV  0.2f
#define NEGV    -9e15f

#define BSTRIDE 136   // padded k-stride (odd 16B units)

// ---------------- device scratch ----------------
__device__ __align__(16) float g_S1[FIN];
__device__ __align__(16) float g_Q1[FIN];
__device__ __align__(16) float g_cvec[FHID];
__device__ __align__(16) float g_S2[FHID];
__device__ __align__(16) float g_Q2[FHID];
__device__ __align__(16) float g_p[FHID];
__device__ __align__(16) float g_q[FHID];
__device__ __align__(16) float g_S3[2];
__device__ __align__(16) float g_s3b3[2];
__device__ __align__(16) __nv_bfloat16 g_Bh[FHID*BSTRIDE];
__device__ __align__(16) __nv_bfloat16 g_Bl[FHID*BSTRIDE];
__device__ __align__(16) float g_ybuf[(size_t)MROWS*FHID];  // 256MB
__device__ __align__(16) float g_zbuf[MROWS];

__device__ __forceinline__ float leakyf(float x){ return x >= 0.f ? x : ALPHAV*x; }

__device__ __forceinline__ uint32_t smem_u32(const void* p){
    uint32_t a;
    asm("{ .reg .u64 t; cvta.to.shared.u64 t, %1; cvt.u32.u64 %0, t; }" : "=r"(a) : "l"(p));
    return a;
}
__device__ __forceinline__ void ldm_x4(uint32_t* r, uint32_t addr){
    asm volatile("ldmatrix.sync.aligned.m8n8.x4.shared.b16 {%0,%1,%2,%3}, [%4];"
                 : "=r"(r[0]), "=r"(r[1]), "=r"(r[2]), "=r"(r[3]) : "r"(addr));
}
__device__ __forceinline__ void mma_bf16(float* c, const uint32_t* a, const uint32_t* b){
    asm volatile("mma.sync.aligned.m16n8k16.row.col.f32.bf16.bf16.f32 "
        "{%0,%1,%2,%3}, {%4,%5,%6,%7}, {%8,%9}, {%0,%1,%2,%3};"
        : "+f"(c[0]), "+f"(c[1]), "+f"(c[2]), "+f"(c[3])
        : "r"(a[0]), "r"(a[1]), "r"(a[2]), "r"(a[3]), "r"(b[0]), "r"(b[1]));
}
// pack two floats -> bf16x2 {hi=b, lo=a}
__device__ __forceinline__ uint32_t pack_bf2(float a, float b){
    uint32_t r;
    asm("cvt.rn.bf16x2.f32 %0, %1, %2;" : "=r"(r) : "f"(b), "f"(a));
    return r;
}
__device__ __forceinline__ unsigned short f2bf_hi(float f, float& rem){
    __nv_bfloat16 h = __float2bfloat16(f);
    rem = f - __bfloat162float(h);
    return *reinterpret_cast<unsigned short*>(&h);
}
__device__ __forceinline__ unsigned short f2bf(float f){
    __nv_bfloat16 h = __float2bfloat16(f);
    return *reinterpret_cast<unsigned short*>(&h);
}

// ---------------- K0 ----------------
__global__ void k_zero(){
    int t = threadIdx.x;
    if (t < FIN){ g_S1[t]=0.f; g_Q1[t]=0.f; }
    if (t < FHID){ g_S2[t]=0.f; g_Q2[t]=0.f; }
    if (t < 2) g_S3[t]=0.f;
}

// ---------------- K1: col stats of adj (MLP=8) ----------------
__global__ __launch_bounds__(256) void k_colstats(const float* __restrict__ adj){
    const int lane = threadIdx.x & 31;
    const int warp = (blockIdx.x*blockDim.x + threadIdx.x) >> 5;
    const int nw   = (gridDim.x*blockDim.x) >> 5;
    float s0=0.f,s1=0.f,s2=0.f,s3=0.f,q0=0.f,q1=0.f,q2=0.f,q3=0.f;
    for (int r = warp*8; r < MROWS; r += nw*8){
        float4 v[8];
        #pragma unroll
        for (int i = 0; i < 8; i++)
            v[i] = *reinterpret_cast<const float4*>(adj + (size_t)(r+i)*FIN + lane*4);
        #pragma unroll
        for (int i = 0; i < 8; i++){
            s0+=v[i].x; q0+=v[i].x*v[i].x;
            s1+=v[i].y; q1+=v[i].y*v[i].y;
            s2+=v[i].z; q2+=v[i].z*v[i].z;
            s3+=v[i].w; q3+=v[i].w*v[i].w;
        }
    }
    __shared__ float bs[FIN], bq[FIN];
    if (threadIdx.x < FIN){ bs[threadIdx.x]=0.f; bq[threadIdx.x]=0.f; }
    __syncthreads();
    atomicAdd(&bs[lane*4+0], s0); atomicAdd(&bs[lane*4+1], s1);
    atomicAdd(&bs[lane*4+2], s2); atomicAdd(&bs[lane*4+3], s3);
    atomicAdd(&bq[lane*4+0], q0); atomicAdd(&bq[lane*4+1], q1);
    atomicAdd(&bq[lane*4+2], q2); atomicAdd(&bq[lane*4+3], q3);
    __syncthreads();
    if (threadIdx.x < FIN){
        atomicAdd(&g_S1[threadIdx.x], bs[threadIdx.x]);
        atomicAdd(&g_Q1[threadIdx.x], bq[threadIdx.x]);
    }
}

// ---------------- K2: fold BN1 into W -> bf16 hi/lo images [n][k] ----------------
__global__ void k_fold1(const float* __restrict__ W,
                        const float* __restrict__ gamma1,
                        const float* __restrict__ beta1){
    __shared__ float s1s[FIN], b1s[FIN];
    int t = threadIdx.x;
    if (t < FIN){
        float mu  = g_S1[t] * (1.f/(float)MROWS);
        float var = g_Q1[t] * (1.f/(float)MROWS) - mu*mu;
        float sc  = gamma1[t] * rsqrtf(var + EPSV);
        s1s[t] = sc;
        b1s[t] = beta1[t] - mu*sc;
    }
    __syncthreads();
    for (int i = t; i < FIN*FHID; i += blockDim.x){
        int k = i >> 6, n = i & 63;
        float w1 = s1s[k] * W[i];
        float rem;
        unsigned short h = f2bf_hi(w1, rem);
        unsigned short l = f2bf(rem);
        reinterpret_cast<unsigned short*>(g_Bh)[n*BSTRIDE + k] = h;
        reinterpret_cast<unsigned short*>(g_Bl)[n*BSTRIDE + k] = l;
    }
    if (t < FHID){
        float acc = 0.f;
        for (int j = 0; j < FIN; j++) acc += b1s[j] * W[j*FHID + t];
        g_cvec[t] = acc;
    }
}

// ---------------- K3: HMMA GEMM y = bn1(x)@W + c, 256 threads, 2 CTA/SM ---------
#define SOFF_AH 0
#define SOFF_AL 34816
#define SOFF_BH 69632
#define SOFF_BL 87040
#define SMEM_TOT 104448

__global__ void __launch_bounds__(256, 2) k_gemm(const float* __restrict__ adj){
    extern __shared__ __align__(1024) char smem[];
    const uint32_t sb = smem_u32(smem);
    const int t = threadIdx.x;
    const int w = t >> 5, lane = t & 31;
    const int g  = lane >> 2, tc = lane & 3;
    const int row0 = blockIdx.x * 128;

    __shared__ float cs[FHID], cq[FHID];
    if (t < FHID){ cs[t]=0.f; cq[t]=0.f; }

    // A staging, phase 1: issue ALL 16 LDG.128 first (MLP=16)
    float4 buf[16];
    {
        const int r = t >> 1, half = t & 1;
        const float4* src = reinterpret_cast<const float4*>(adj + (size_t)(row0 + r)*FIN + half*64);
        #pragma unroll
        for (int i = 0; i < 16; i++) buf[i] = src[i];
    }

    // B: flat copy of prebuilt images (1088 uint4 each)
    {
        const uint4* sh = reinterpret_cast<const uint4*>(g_Bh);
        const uint4* sl = reinterpret_cast<const uint4*>(g_Bl);
        uint4* dh = reinterpret_cast<uint4*>(smem + SOFF_BH);
        uint4* dl = reinterpret_cast<uint4*>(smem + SOFF_BL);
        #pragma unroll
        for (int i = 0; i < 5; i++){
            int idx = t + i*256;
            if (idx < 1088){ dh[idx] = sh[idx]; dl[idx] = sl[idx]; }
        }
    }

    // A staging, phase 2: packed conversion + swizzled store
    {
        const int r = t >> 1, half = t & 1;
        #pragma unroll
        for (int ggi = 0; ggi < 8; ggi++){
            const int gg = ggi ^ (half*4);
            float4 va = buf[gg*2], vb = buf[gg*2+1];
            float v[8] = {va.x,va.y,va.z,va.w,vb.x,vb.y,vb.z,vb.w};
            uint4 ph, pl;
            uint32_t* php = reinterpret_cast<uint32_t*>(&ph);
            uint32_t* plp = reinterpret_cast<uint32_t*>(&pl);
            #pragma unroll
            for (int j = 0; j < 4; j++){
                float a = v[2*j], b = v[2*j+1];
                uint32_t hp = pack_bf2(a, b);
                php[j] = hp;
                float ra = a - __uint_as_float(hp << 16);
                float rb = b - __uint_as_float(hp & 0xFFFF0000u);
                plp[j] = pack_bf2(ra, rb);
            }
            uint32_t off = (uint32_t)(r*BSTRIDE + half*64 + gg*8)*2u;
            *reinterpret_cast<uint4*>(smem + SOFF_AH + off) = ph;
            *reinterpret_cast<uint4*>(smem + SOFF_AL + off) = pl;
        }
    }
    __syncthreads();

    // fragment base addresses: warp w owns rows w*16..w*16+15
    uint32_t aAddr = sb + SOFF_AH +
        (uint32_t)((w*16 + (lane & 15))*BSTRIDE + 8*(lane >> 4))*2u;
    uint32_t bAddr = sb + SOFF_BH +
        (uint32_t)(((lane & 7) + ((lane & 16) >> 1))*BSTRIDE + (lane & 8))*2u;

    float acc[8][4];
    #pragma unroll
    for (int nt = 0; nt < 8; nt++)
        #pragma unroll
        for (int i = 0; i < 4; i++) acc[nt][i] = 0.f;

    #pragma unroll
    for (int ks = 0; ks < 8; ks++){
        const uint32_t kOff = (uint32_t)(ks*16*2);
        uint32_t ah[4], al[4];
        ldm_x4(ah, aAddr + kOff);
        ldm_x4(al, aAddr + kOff + (SOFF_AL - SOFF_AH));
        #pragma unroll
        for (int p = 0; p < 4; p++){
            const uint32_t bo = bAddr + kOff + (uint32_t)(p*16*BSTRIDE*2);
            uint32_t bh[4], bl[4];
            ldm_x4(bh, bo);
            ldm_x4(bl, bo + (SOFF_BL - SOFF_BH));
            // alternate accumulators: RAW distance 2
            mma_bf16(acc[2*p],   ah, bh);
            mma_bf16(acc[2*p+1], ah, bh+2);
            mma_bf16(acc[2*p],   ah, bl);
            mma_bf16(acc[2*p+1], ah, bl+2);
            mma_bf16(acc[2*p],   al, bh);
            mma_bf16(acc[2*p+1], al, bh+2);
        }
    }

    // epilogue: per n-tile — add cvec, write y, reduce stats, atomic
    const int r0 = row0 + w*16 + g;
    const int r1 = r0 + 8;
    #pragma unroll
    for (int nt = 0; nt < 8; nt++){
        const int c0 = nt*8 + 2*tc;
        const float cv0 = __ldg(&g_cvec[c0]);
        const float cv1 = __ldg(&g_cvec[c0+1]);
        float v00 = acc[nt][0] + cv0;
        float v01 = acc[nt][1] + cv1;
        float v10 = acc[nt][2] + cv0;
        float v11 = acc[nt][3] + cv1;
        *reinterpret_cast<float2*>(&g_ybuf[(size_t)r0*FHID + c0]) = make_float2(v00, v01);
        *reinterpret_cast<float2*>(&g_ybuf[(size_t)r1*FHID + c0]) = make_float2(v10, v11);
        float s0 = v00 + v10, q0 = v00*v00 + v10*v10;
        float s1 = v01 + v11, q1 = v01*v01 + v11*v11;
        #pragma unroll
        for (int o = 4; o <= 16; o <<= 1){
            s0 += __shfl_xor_sync(0xffffffffu, s0, o);
            q0 += __shfl_xor_sync(0xffffffffu, q0, o);
            s1 += __shfl_xor_sync(0xffffffffu, s1, o);
            q1 += __shfl_xor_sync(0xffffffffu, q1, o);
        }
        if (lane < 4){
            atomicAdd(&cs[c0  ], s0);
            atomicAdd(&cq[c0  ], q0);
            atomicAdd(&cs[c0+1], s1);
            atomicAdd(&cq[c0+1], q1);
        }
    }
    __syncthreads();
    if (t < FHID){
        atomicAdd(&g_S2[t], cs[t]);
        atomicAdd(&g_Q2[t], cq[t]);
    }
}

// ---------------- K4 ----------------
__global__ void k_fold2(const float* __restrict__ gamma2, const float* __restrict__ beta2){
    int t = threadIdx.x;
    if (t < FHID){
        float mu  = g_S2[t] * (1.f/(float)MROWS);
        float var = g_Q2[t] * (1.f/(float)MROWS) - mu*mu;
        float sc  = gamma2[t] * rsqrtf(var + EPSV);
        g_p[t] = sc;
        g_q[t] = beta2[t] - mu*sc;
    }
}

// ---------------- K5: z pass ----------------
__global__ __launch_bounds__(256) void k_zpass(const float* __restrict__ avec){
    const int t    = threadIdx.x;
    const int lane = t & 31;
    const int g    = lane & 7;
    float pc[8], qc[8], ac[8];
    #pragma unroll
    for (int i = 0; i < 4; i++){
        pc[i]   = g_p[g*4+i];      qc[i]   = g_q[g*4+i];      ac[i]   = avec[g*4+i];
        pc[4+i] = g_p[32+g*4+i];   qc[4+i] = g_q[32+g*4+i];   ac[4+i] = avec[32+g*4+i];
    }
    const int warp = (blockIdx.x*blockDim.x + t) >> 5;
    const int nw   = (gridDim.x*blockDim.x) >> 5;
    float zs = 0.f, zq = 0.f;
    for (int base = warp*8; base < MROWS; base += nw*8){
        #pragma unroll
        for (int h = 0; h < 2; h++){
            int row = base + h*4 + (lane >> 3);
            const float4 v0 = *reinterpret_cast<const float4*>(&g_ybuf[(size_t)row*FHID + g*4]);
            const float4 v1 = *reinterpret_cast<const float4*>(&g_ybuf[(size_t)row*FHID + 32 + g*4]);
            float z = 0.f;
            z += leakyf(v0.x*pc[0]+qc[0])*ac[0];
            z += leakyf(v0.y*pc[1]+qc[1])*ac[1];
            z += leakyf(v0.z*pc[2]+qc[2])*ac[2];
            z += leakyf(v0.w*pc[3]+qc[3])*ac[3];
            z += leakyf(v1.x*pc[4]+qc[4])*ac[4];
            z += leakyf(v1.y*pc[5]+qc[5])*ac[5];
            z += leakyf(v1.z*pc[6]+qc[6])*ac[6];
            z += leakyf(v1.w*pc[7]+qc[7])*ac[7];
            z += __shfl_xor_sync(0xffffffffu, z, 1);
            z += __shfl_xor_sync(0xffffffffu, z, 2);
            z += __shfl_xor_sync(0xffffffffu, z, 4);
            if (g == 0){
                g_zbuf[row] = z;
                zs += z; zq += z*z;
            }
        }
    }
    #pragma unroll
    for (int o = 16; o > 0; o >>= 1){
        zs += __shfl_xor_sync(0xffffffffu, zs, o);
        zq += __shfl_xor_sync(0xffffffffu, zq, o);
    }
    if (lane == 0){
        atomicAdd(&g_S3[0], zs);
        atomicAdd(&g_S3[1], zq);
    }
}

// ---------------- K6 ----------------
__global__ void k_fold3(const float* __restrict__ gamma3, const float* __restrict__ beta3){
    float mu  = g_S3[0] * (1.f/(float)MROWS);
    float var = g_S3[1] * (1.f/(float)MROWS) - mu*mu;
    float sc  = gamma3[0] * rsqrtf(var + EPSV);
    g_s3b3[0] = sc;
    g_s3b3[1] = beta3[0] - mu*sc;
}

// ---------------- K7: masked row softmax ----------------
__global__ __launch_bounds__(256) void k_softmax(const float* __restrict__ adj_mean,
                                                 float* __restrict__ out){
    const int row = blockIdx.x;
    const int t   = threadIdx.x;
    const int lane = t & 31, wid = t >> 5;
    const float s3 = g_s3b3[0], b3 = g_s3b3[1];

    const float4 zv = *reinterpret_cast<const float4*>(&g_zbuf[(size_t)row*NROWS + t*4]);
    const float4 mv = *reinterpret_cast<const float4*>(&adj_mean[(size_t)row*NROWS + t*4]);
    float v[4];
    {
        float zz[4] = {zv.x, zv.y, zv.z, zv.w};
        float mm[4] = {mv.x, mv.y, mv.z, mv.w};
        #pragma unroll
        for (int i = 0; i < 4; i++){
            float e = leakyf(zz[i]*s3 + b3);
            v[i] = (mm[i] > 0.f) ? e : NEGV;
        }
    }
    __shared__ float sred[8];
    float mx = fmaxf(fmaxf(v[0],v[1]), fmaxf(v[2],v[3]));
    #pragma unroll
    for (int o = 16; o > 0; o >>= 1) mx = fmaxf(mx, __shfl_xor_sync(0xffffffffu, mx, o));
    if (lane == 0) sred[wid] = mx;
    __syncthreads();
    if (t < 32){
        float m2 = (t < 8) ? sred[t] : -3.4e38f;
        #pragma unroll
        for (int o = 4; o > 0; o >>= 1) m2 = fmaxf(m2, __shfl_xor_sync(0xffffffffu, m2, o));
        if (t == 0) sred[0] = m2;
    }
    __syncthreads();
    mx = sred[0];
    __syncthreads();
    float e[4];
    #pragma unroll
    for (int i = 0; i < 4; i++) e[i] = __expf(v[i] - mx);
    float se = e[0]+e[1]+e[2]+e[3];
    #pragma unroll
    for (int o = 16; o > 0; o >>= 1) se += __shfl_xor_sync(0xffffffffu, se, o);
    if (lane == 0) sred[wid] = se;
    __syncthreads();
    if (t < 32){
        float s2 = (t < 8) ? sred[t] : 0.f;
        #pragma unroll
        for (int o = 4; o > 0; o >>= 1) s2 += __shfl_xor_sync(0xffffffffu, s2, o);
        if (t == 0) sred[0] = s2;
    }
    __syncthreads();
    const float inv = 1.f / sred[0];
    float4 ov = make_float4(e[0]*inv, e[1]*inv, e[2]*inv, e[3]*inv);
    *reinterpret_cast<float4*>(&out[(size_t)row*NROWS + t*4]) = ov;
}

// ---------------- launch ----------------
extern "C" void kernel_launch(void* const* d_in, const int* in_sizes, int n_in,
                              void* d_out, int out_size){
    const float* adj      = (const float*)d_in[0];
    const float* adj_mean = (const float*)d_in[1];
    const float* W        = (const float*)d_in[2];
    const float* a        = (const float*)d_in[3];
    const float* gamma1   = (const float*)d_in[4];
    const float* beta1    = (const float*)d_in[5];
    const float* gamma2   = (const float*)d_in[6];
    const float* beta2    = (const float*)d_in[7];
    const float* gamma3   = (const float*)d_in[8];
    const float* beta3    = (const float*)d_in[9];
    float* out = (float*)d_out;

    cudaFuncSetAttribute(k_gemm, cudaFuncAttributeMaxDynamicSharedMemorySize, SMEM_TOT);

    k_zero    <<<1, 128>>>();
    k_colstats<<<4096, 256>>>(adj);
    k_fold1   <<<1, 256>>>(W, gamma1, beta1);
    k_gemm    <<<MROWS/128, 256, SMEM_TOT>>>(adj);
    k_fold2   <<<1, 64>>>(gamma2, beta2);
    k_zpass   <<<2048, 256>>>(a);
    k_fold3   <<<1, 1>>>(gamma3, beta3);
    k_softmax <<<NROWS, 256>>>(adj_mean, out);
}

// round 8
// speedup vs baseline: 1.2903x; 1.2903x over previous
#include <cuda_runtime.h>
#include <cuda_bf16.h>
#include <cstdint>
#include <cstddef>

#define NROWS   1024
#define MROWS   (NROWS*NROWS)
#define FIN     128
#define FHID    64
#define EPSV    1e-5f
#define ALPHAV  0.2f
#define NEGV    -9e15f

#define BSTRIDE 136   // B k-stride in bf16 (272B rows)
#define ASTRIDE 72    // A k-stride in bf16 (144B rows), half-K tile

// ---------------- device scratch ----------------
__device__ __align__(16) float g_S1[FIN];
__device__ __align__(16) float g_Q1[FIN];
__device__ __align__(16) float g_cvec[FHID];
__device__ __align__(16) float g_S2[FHID];
__device__ __align__(16) float g_Q2[FHID];
__device__ __align__(16) float g_p[FHID];
__device__ __align__(16) float g_q[FHID];
__device__ __align__(16) float g_S3[2];
__device__ __align__(16) float g_s3b3[2];
__device__ __align__(16) __nv_bfloat16 g_Bh[FHID*BSTRIDE];
__device__ __align__(16) __nv_bfloat16 g_Bl[FHID*BSTRIDE];
__device__ __align__(16) float g_ybuf[(size_t)MROWS*FHID];  // 256MB
__device__ __align__(16) float g_zbuf[MROWS];

__device__ __forceinline__ float leakyf(float x){ return x >= 0.f ? x : ALPHAV*x; }

__device__ __forceinline__ uint32_t smem_u32(const void* p){
    uint32_t a;
    asm("{ .reg .u64 t; cvta.to.shared.u64 t, %1; cvt.u32.u64 %0, t; }" : "=r"(a) : "l"(p));
    return a;
}
__device__ __forceinline__ void ldm_x4(uint32_t* r, uint32_t addr){
    asm volatile("ldmatrix.sync.aligned.m8n8.x4.shared.b16 {%0,%1,%2,%3}, [%4];"
                 : "=r"(r[0]), "=r"(r[1]), "=r"(r[2]), "=r"(r[3]) : "r"(addr));
}
__device__ __forceinline__ void mma_bf16(float* c, const uint32_t* a, const uint32_t* b){
    asm volatile("mma.sync.aligned.m16n8k16.row.col.f32.bf16.bf16.f32 "
        "{%0,%1,%2,%3}, {%4,%5,%6,%7}, {%8,%9}, {%0,%1,%2,%3};"
        : "+f"(c[0]), "+f"(c[1]), "+f"(c[2]), "+f"(c[3])
        : "r"(a[0]), "r"(a[1]), "r"(a[2]), "r"(a[3]), "r"(b[0]), "r"(b[1]));
}
__device__ __forceinline__ unsigned short f2bf_hi(float f, float& rem){
    __nv_bfloat16 h = __float2bfloat16(f);
    rem = f - __bfloat162float(h);
    return *reinterpret_cast<unsigned short*>(&h);
}
__device__ __forceinline__ unsigned short f2bf(float f){
    __nv_bfloat16 h = __float2bfloat16(f);
    return *reinterpret_cast<unsigned short*>(&h);
}

// ---------------- K0 ----------------
__global__ void k_zero(){
    int t = threadIdx.x;
    if (t < FIN){ g_S1[t]=0.f; g_Q1[t]=0.f; }
    if (t < FHID){ g_S2[t]=0.f; g_Q2[t]=0.f; }
    if (t < 2) g_S3[t]=0.f;
}

// ---------------- K1: col stats of adj (MLP=8) ----------------
__global__ __launch_bounds__(256) void k_colstats(const float* __restrict__ adj){
    const int lane = threadIdx.x & 31;
    const int warp = (blockIdx.x*blockDim.x + threadIdx.x) >> 5;
    const int nw   = (gridDim.x*blockDim.x) >> 5;
    float s0=0.f,s1=0.f,s2=0.f,s3=0.f,q0=0.f,q1=0.f,q2=0.f,q3=0.f;
    for (int r = warp*8; r < MROWS; r += nw*8){
        float4 v[8];
        #pragma unroll
        for (int i = 0; i < 8; i++)
            v[i] = *reinterpret_cast<const float4*>(adj + (size_t)(r+i)*FIN + lane*4);
        #pragma unroll
        for (int i = 0; i < 8; i++){
            s0+=v[i].x; q0+=v[i].x*v[i].x;
            s1+=v[i].y; q1+=v[i].y*v[i].y;
            s2+=v[i].z; q2+=v[i].z*v[i].z;
            s3+=v[i].w; q3+=v[i].w*v[i].w;
        }
    }
    __shared__ float bs[FIN], bq[FIN];
    if (threadIdx.x < FIN){ bs[threadIdx.x]=0.f; bq[threadIdx.x]=0.f; }
    __syncthreads();
    atomicAdd(&bs[lane*4+0], s0); atomicAdd(&bs[lane*4+1], s1);
    atomicAdd(&bs[lane*4+2], s2); atomicAdd(&bs[lane*4+3], s3);
    atomicAdd(&bq[lane*4+0], q0); atomicAdd(&bq[lane*4+1], q1);
    atomicAdd(&bq[lane*4+2], q2); atomicAdd(&bq[lane*4+3], q3);
    __syncthreads();
    if (threadIdx.x < FIN){
        atomicAdd(&g_S1[threadIdx.x], bs[threadIdx.x]);
        atomicAdd(&g_Q1[threadIdx.x], bq[threadIdx.x]);
    }
}

// ---------------- K2: fold BN1 into W -> bf16 hi/lo images [n][k] ----------------
__global__ void k_fold1(const float* __restrict__ W,
                        const float* __restrict__ gamma1,
                        const float* __restrict__ beta1){
    __shared__ float s1s[FIN], b1s[FIN];
    int t = threadIdx.x;
    if (t < FIN){
        float mu  = g_S1[t] * (1.f/(float)MROWS);
        float var = g_Q1[t] * (1.f/(float)MROWS) - mu*mu;
        float sc  = gamma1[t] * rsqrtf(var + EPSV);
        s1s[t] = sc;
        b1s[t] = beta1[t] - mu*sc;
    }
    __syncthreads();
    for (int i = t; i < FIN*FHID; i += blockDim.x){
        int k = i >> 6, n = i & 63;
        float w1 = s1s[k] * W[i];
        float rem;
        unsigned short h = f2bf_hi(w1, rem);
        unsigned short l = f2bf(rem);
        reinterpret_cast<unsigned short*>(g_Bh)[n*BSTRIDE + k] = h;
        reinterpret_cast<unsigned short*>(g_Bl)[n*BSTRIDE + k] = l;
    }
    if (t < FHID){
        float acc = 0.f;
        for (int j = 0; j < FIN; j++) acc += b1s[j] * W[j*FHID + t];
        g_cvec[t] = acc;
    }
}

// ---------------- K3: HMMA GEMM, 256-row CTA, M=32/warp, K-split staging --------
#define SOFF_AH 0
#define SOFF_AL 36864
#define SOFF_BH 73728
#define SOFF_BL 91136
#define SMEM_TOT 108544

__global__ void __launch_bounds__(256, 2) k_gemm(const float* __restrict__ adj){
    extern __shared__ __align__(1024) char smem[];
    const uint32_t sb = smem_u32(smem);
    const int t = threadIdx.x;
    const int w = t >> 5, lane = t & 31;
    const int g  = lane >> 2, tc = lane & 3;
    const int row0 = blockIdx.x * 256;

    __shared__ float cs[FHID], cq[FHID];
    if (t < FHID){ cs[t]=0.f; cq[t]=0.f; }

    // B: flat copy of prebuilt images (1088 uint4 each), once
    {
        const uint4* sh = reinterpret_cast<const uint4*>(g_Bh);
        const uint4* sl = reinterpret_cast<const uint4*>(g_Bl);
        uint4* dh = reinterpret_cast<uint4*>(smem + SOFF_BH);
        uint4* dl = reinterpret_cast<uint4*>(smem + SOFF_BL);
        #pragma unroll
        for (int i = 0; i < 5; i++){
            int idx = t + i*256;
            if (idx < 1088){ dh[idx] = sh[idx]; dl[idx] = sl[idx]; }
        }
    }

    // fragment base addresses: warp w owns rows w*32..w*32+31 (2 m-tiles of 16)
    const uint32_t aBase = sb + SOFF_AH +
        (uint32_t)((w*32 + (lane & 15))*ASTRIDE + 8*(lane >> 4))*2u;
    const uint32_t bBase = sb + SOFF_BH +
        (uint32_t)(((lane & 7) + ((lane & 16) >> 1))*BSTRIDE + (lane & 8))*2u;

    float acc[2][8][4];
    #pragma unroll
    for (int mt = 0; mt < 2; mt++)
        #pragma unroll
        for (int nt = 0; nt < 8; nt++)
            #pragma unroll
            for (int i = 0; i < 4; i++) acc[mt][nt][i] = 0.f;

    #pragma unroll
    for (int ph = 0; ph < 2; ph++){
        if (ph == 1) __syncthreads();   // all warps done reading phase-0 A
        // stage A phase: thread t = row t, k in [ph*64, ph*64+64)
        {
            const int r = t;
            const float4* src = reinterpret_cast<const float4*>(
                adj + (size_t)(row0 + r)*FIN + ph*64);
            #pragma unroll
            for (int gg = 0; gg < 8; gg++){
                float4 va = src[gg*2], vb = src[gg*2+1];
                float v[8] = {va.x,va.y,va.z,va.w,vb.x,vb.y,vb.z,vb.w};
                unsigned short hh[8], ll[8];
                #pragma unroll
                for (int j = 0; j < 8; j++){
                    float rem;
                    hh[j] = f2bf_hi(v[j], rem);
                    ll[j] = f2bf(rem);
                }
                uint4 phv, plv;
                phv.x = (uint32_t)hh[0] | ((uint32_t)hh[1]<<16);
                phv.y = (uint32_t)hh[2] | ((uint32_t)hh[3]<<16);
                phv.z = (uint32_t)hh[4] | ((uint32_t)hh[5]<<16);
                phv.w = (uint32_t)hh[6] | ((uint32_t)hh[7]<<16);
                plv.x = (uint32_t)ll[0] | ((uint32_t)ll[1]<<16);
                plv.y = (uint32_t)ll[2] | ((uint32_t)ll[3]<<16);
                plv.z = (uint32_t)ll[4] | ((uint32_t)ll[5]<<16);
                plv.w = (uint32_t)ll[6] | ((uint32_t)ll[7]<<16);
                uint32_t off = (uint32_t)(r*ASTRIDE + gg*8)*2u;
                *reinterpret_cast<uint4*>(smem + SOFF_AH + off) = phv;
                *reinterpret_cast<uint4*>(smem + SOFF_AL + off) = plv;
            }
        }
        __syncthreads();

        #pragma unroll
        for (int ksl = 0; ksl < 4; ksl++){
            const uint32_t kA = (uint32_t)(ksl*32);            // 16 bf16 = 32B
            const uint32_t kB = (uint32_t)((ph*4 + ksl)*32);
            uint32_t ah0[4], al0[4], ah1[4], al1[4];
            ldm_x4(ah0, aBase + kA);
            ldm_x4(al0, aBase + kA + (SOFF_AL - SOFF_AH));
            ldm_x4(ah1, aBase + kA + (uint32_t)(16*ASTRIDE*2));
            ldm_x4(al1, aBase + kA + (uint32_t)(16*ASTRIDE*2) + (SOFF_AL - SOFF_AH));
            #pragma unroll
            for (int p = 0; p < 4; p++){
                const uint32_t bo = bBase + kB + (uint32_t)(p*16*BSTRIDE*2);
                uint32_t bh[4], bl[4];
                ldm_x4(bh, bo);
                ldm_x4(bl, bo + (SOFF_BL - SOFF_BH));
                // mt-interleaved: RAW distance 4
                mma_bf16(acc[0][2*p],   ah0, bh);
                mma_bf16(acc[1][2*p],   ah1, bh);
                mma_bf16(acc[0][2*p+1], ah0, bh+2);
                mma_bf16(acc[1][2*p+1], ah1, bh+2);
                mma_bf16(acc[0][2*p],   ah0, bl);
                mma_bf16(acc[1][2*p],   ah1, bl);
                mma_bf16(acc[0][2*p+1], ah0, bl+2);
                mma_bf16(acc[1][2*p+1], ah1, bl+2);
                mma_bf16(acc[0][2*p],   al0, bh);
                mma_bf16(acc[1][2*p],   al1, bh);
                mma_bf16(acc[0][2*p+1], al0, bh+2);
                mma_bf16(acc[1][2*p+1], al1, bh+2);
            }
        }
    }

    // epilogue: per n-tile — add cvec, write y (4 rows/thread), one reduce
    #pragma unroll
    for (int nt = 0; nt < 8; nt++){
        const int c0 = nt*8 + 2*tc;
        const float cv0 = __ldg(&g_cvec[c0]);
        const float cv1 = __ldg(&g_cvec[c0+1]);
        float s0 = 0.f, q0 = 0.f, s1 = 0.f, q1 = 0.f;
        #pragma unroll
        for (int mt = 0; mt < 2; mt++){
            const int r0 = row0 + w*32 + mt*16 + g;
            const int r1 = r0 + 8;
            float v00 = acc[mt][nt][0] + cv0;
            float v01 = acc[mt][nt][1] + cv1;
            float v10 = acc[mt][nt][2] + cv0;
            float v11 = acc[mt][nt][3] + cv1;
            *reinterpret_cast<float2*>(&g_ybuf[(size_t)r0*FHID + c0]) = make_float2(v00, v01);
            *reinterpret_cast<float2*>(&g_ybuf[(size_t)r1*FHID + c0]) = make_float2(v10, v11);
            s0 += v00 + v10;  q0 += v00*v00 + v10*v10;
            s1 += v01 + v11;  q1 += v01*v01 + v11*v11;
        }
        #pragma unroll
        for (int o = 4; o <= 16; o <<= 1){
            s0 += __shfl_xor_sync(0xffffffffu, s0, o);
            q0 += __shfl_xor_sync(0xffffffffu, q0, o);
            s1 += __shfl_xor_sync(0xffffffffu, s1, o);
            q1 += __shfl_xor_sync(0xffffffffu, q1, o);
        }
        if (lane < 4){
            atomicAdd(&cs[c0  ], s0);
            atomicAdd(&cq[c0  ], q0);
            atomicAdd(&cs[c0+1], s1);
            atomicAdd(&cq[c0+1], q1);
        }
    }
    __syncthreads();
    if (t < FHID){
        atomicAdd(&g_S2[t], cs[t]);
        atomicAdd(&g_Q2[t], cq[t]);
    }
}

// ---------------- K4 ----------------
__global__ void k_fold2(const float* __restrict__ gamma2, const float* __restrict__ beta2){
    int t = threadIdx.x;
    if (t < FHID){
        float mu  = g_S2[t] * (1.f/(float)MROWS);
        float var = g_Q2[t] * (1.f/(float)MROWS) - mu*mu;
        float sc  = gamma2[t] * rsqrtf(var + EPSV);
        g_p[t] = sc;
        g_q[t] = beta2[t] - mu*sc;
    }
}

// ---------------- K5: z pass ----------------
__global__ __launch_bounds__(256) void k_zpass(const float* __restrict__ avec){
    const int t    = threadIdx.x;
    const int lane = t & 31;
    const int g    = lane & 7;
    float pc[8], qc[8], ac[8];
    #pragma unroll
    for (int i = 0; i < 4; i++){
        pc[i]   = g_p[g*4+i];      qc[i]   = g_q[g*4+i];      ac[i]   = avec[g*4+i];
        pc[4+i] = g_p[32+g*4+i];   qc[4+i] = g_q[32+g*4+i];   ac[4+i] = avec[32+g*4+i];
    }
    const int warp = (blockIdx.x*blockDim.x + t) >> 5;
    const int nw   = (gridDim.x*blockDim.x) >> 5;
    float zs = 0.f, zq = 0.f;
    for (int base = warp*8; base < MROWS; base += nw*8){
        #pragma unroll
        for (int h = 0; h < 2; h++){
            int row = base + h*4 + (lane >> 3);
            const float4 v0 = *reinterpret_cast<const float4*>(&g_ybuf[(size_t)row*FHID + g*4]);
            const float4 v1 = *reinterpret_cast<const float4*>(&g_ybuf[(size_t)row*FHID + 32 + g*4]);
            float z = 0.f;
            z += leakyf(v0.x*pc[0]+qc[0])*ac[0];
            z += leakyf(v0.y*pc[1]+qc[1])*ac[1];
            z += leakyf(v0.z*pc[2]+qc[2])*ac[2];
            z += leakyf(v0.w*pc[3]+qc[3])*ac[3];
            z += leakyf(v1.x*pc[4]+qc[4])*ac[4];
            z += leakyf(v1.y*pc[5]+qc[5])*ac[5];
            z += leakyf(v1.z*pc[6]+qc[6])*ac[6];
            z += leakyf(v1.w*pc[7]+qc[7])*ac[7];
            z += __shfl_xor_sync(0xffffffffu, z, 1);
            z += __shfl_xor_sync(0xffffffffu, z, 2);
            z += __shfl_xor_sync(0xffffffffu, z, 4);
            if (g == 0){
                g_zbuf[row] = z;
                zs += z; zq += z*z;
            }
        }
    }
    #pragma unroll
    for (int o = 16; o > 0; o >>= 1){
        zs += __shfl_xor_sync(0xffffffffu, zs, o);
        zq += __shfl_xor_sync(0xffffffffu, zq, o);
    }
    if (lane == 0){
        atomicAdd(&g_S3[0], zs);
        atomicAdd(&g_S3[1], zq);
    }
}

// ---------------- K6 ----------------
__global__ void k_fold3(const float* __restrict__ gamma3, const float* __restrict__ beta3){
    float mu  = g_S3[0] * (1.f/(float)MROWS);
    float var = g_S3[1] * (1.f/(float)MROWS) - mu*mu;
    float sc  = gamma3[0] * rsqrtf(var + EPSV);
    g_s3b3[0] = sc;
    g_s3b3[1] = beta3[0] - mu*sc;
}

// ---------------- K7: masked row softmax ----------------
__global__ __launch_bounds__(256) void k_softmax(const float* __restrict__ adj_mean,
                                                 float* __restrict__ out){
    const int row = blockIdx.x;
    const int t   = threadIdx.x;
    const int lane = t & 31, wid = t >> 5;
    const float s3 = g_s3b3[0], b3 = g_s3b3[1];

    const float4 zv = *reinterpret_cast<const float4*>(&g_zbuf[(size_t)row*NROWS + t*4]);
    const float4 mv = *reinterpret_cast<const float4*>(&adj_mean[(size_t)row*NROWS + t*4]);
    float v[4];
    {
        float zz[4] = {zv.x, zv.y, zv.z, zv.w};
        float mm[4] = {mv.x, mv.y, mv.z, mv.w};
        #pragma unroll
        for (int i = 0; i < 4; i++){
            float e = leakyf(zz[i]*s3 + b3);
            v[i] = (mm[i] > 0.f) ? e : NEGV;
        }
    }
    __shared__ float sred[8];
    float mx = fmaxf(fmaxf(v[0],v[1]), fmaxf(v[2],v[3]));
    #pragma unroll
    for (int o = 16; o > 0; o >>= 1) mx = fmaxf(mx, __shfl_xor_sync(0xffffffffu, mx, o));
    if (lane == 0) sred[wid] = mx;
    __syncthreads();
    if (t < 32){
        float m2 = (t < 8) ? sred[t] : -3.4e38f;
        #pragma unroll
        for (int o = 4; o > 0; o >>= 1) m2 = fmaxf(m2, __shfl_xor_sync(0xffffffffu, m2, o));
        if (t == 0) sred[0] = m2;
    }
    __syncthreads();
    mx = sred[0];
    __syncthreads();
    float e[4];
    #pragma unroll
    for (int i = 0; i < 4; i++) e[i] = __expf(v[i] - mx);
    float se = e[0]+e[1]+e[2]+e[3];
    #pragma unroll
    for (int o = 16; o > 0; o >>= 1) se += __shfl_xor_sync(0xffffffffu, se, o);
    if (lane == 0) sred[wid] = se;
    __syncthreads();
    if (t < 32){
        float s2 = (t < 8) ? sred[t] : 0.f;
        #pragma unroll
        for (int o = 4; o > 0; o >>= 1) s2 += __shfl_xor_sync(0xffffffffu, s2, o);
        if (t == 0) sred[0] = s2;
    }
    __syncthreads();
    const float inv = 1.f / sred[0];
    float4 ov = make_float4(e[0]*inv, e[1]*inv, e[2]*inv, e[3]*inv);
    *reinterpret_cast<float4*>(&out[(size_t)row*NROWS + t*4]) = ov;
}

// ---------------- launch ----------------
extern "C" void kernel_launch(void* const* d_in, const int* in_sizes, int n_in,
                              void* d_out, int out_size){
    const float* adj      = (const float*)d_in[0];
    const float* adj_mean = (const float*)d_in[1];
    const float* W        = (const float*)d_in[2];
    const float* a        = (const float*)d_in[3];
    const float* gamma1   = (const float*)d_in[4];
    const float* beta1    = (const float*)d_in[5];
    const float* gamma2   = (const float*)d_in[6];
    const float* beta2    = (const float*)d_in[7];
    const float* gamma3   = (const float*)d_in[8];
    const float* beta3    = (const float*)d_in[9];
    float* out = (float*)d_out;

    cudaFuncSetAttribute(k_gemm, cudaFuncAttributeMaxDynamicSharedMemorySize, SMEM_TOT);

    k_zero    <<<1, 128>>>();
    k_colstats<<<4096, 256>>>(adj);
    k_fold1   <<<1, 256>>>(W, gamma1, beta1);
    k_gemm    <<<MROWS/256, 256, SMEM_TOT>>>(adj);
    k_fold2   <<<1, 64>>>(gamma2, beta2);
    k_zpass   <<<2048, 256>>>(a);
    k_fold3   <<<1, 1>>>(gamma3, beta3);
    k_softmax <<<NROWS, 256>>>(adj_mean, out);
}

// round 9
// speedup vs baseline: 1.4300x; 1.1083x over previous
#include <cuda_runtime.h>
#include <cuda_bf16.h>
#include <cstdint>
#include <cstddef>

#define NROWS   1024
#define MROWS   (NROWS*NROWS)
#define FIN     128
#define FHID    64
#define EPSV    1e-5f
#define ALPHAV  0.2f
#define NEGV    -9e15f

#define BSTRIDE 136   // B k-stride in bf16 (272B rows)
#define ASTRIDE 72    // A k-stride in bf16 (144B rows), half-K tile

// ---------------- device scratch ----------------
__device__ __align__(16) float g_S1[FIN];
__device__ __align__(16) float g_Q1[FIN];
__device__ __align__(16) float g_cvec[FHID];
__device__ __align__(16) float g_S2[FHID];
__device__ __align__(16) float g_Q2[FHID];
__device__ __align__(16) float g_p[FHID];
__device__ __align__(16) float g_q[FHID];
__device__ __align__(16) float g_S3[2];
__device__ __align__(16) float g_s3b3[2];
__device__ __align__(16) __nv_bfloat16 g_Bh[FHID*BSTRIDE];
__device__ __align__(16) __nv_bfloat16 g_Bl[FHID*BSTRIDE];
__device__ __align__(16) uint4 g_Ah[(size_t)MROWS*16];      // 256MB bf16-hi plane [row][128]
__device__ __align__(16) uint4 g_Al[(size_t)MROWS*16];      // 256MB bf16-lo plane
__device__ __align__(16) float g_ybuf[(size_t)MROWS*FHID];  // 256MB
__device__ __align__(16) float g_zbuf[MROWS];

__device__ __forceinline__ float leakyf(float x){ return x >= 0.f ? x : ALPHAV*x; }

__device__ __forceinline__ uint32_t smem_u32(const void* p){
    uint32_t a;
    asm("{ .reg .u64 t; cvta.to.shared.u64 t, %1; cvt.u32.u64 %0, t; }" : "=r"(a) : "l"(p));
    return a;
}
__device__ __forceinline__ void ldm_x4(uint32_t* r, uint32_t addr){
    asm volatile("ldmatrix.sync.aligned.m8n8.x4.shared.b16 {%0,%1,%2,%3}, [%4];"
                 : "=r"(r[0]), "=r"(r[1]), "=r"(r[2]), "=r"(r[3]) : "r"(addr));
}
__device__ __forceinline__ void mma_bf16(float* c, const uint32_t* a, const uint32_t* b){
    asm volatile("mma.sync.aligned.m16n8k16.row.col.f32.bf16.bf16.f32 "
        "{%0,%1,%2,%3}, {%4,%5,%6,%7}, {%8,%9}, {%0,%1,%2,%3};"
        : "+f"(c[0]), "+f"(c[1]), "+f"(c[2]), "+f"(c[3])
        : "r"(a[0]), "r"(a[1]), "r"(a[2]), "r"(a[3]), "r"(b[0]), "r"(b[1]));
}
// pack two floats -> bf16x2 {lo=a, hi=b}
__device__ __forceinline__ uint32_t pack_bf2(float a, float b){
    uint32_t r;
    asm("cvt.rn.bf16x2.f32 %0, %1, %2;" : "=r"(r) : "f"(b), "f"(a));
    return r;
}
__device__ __forceinline__ unsigned short f2bf_hi(float f, float& rem){
    __nv_bfloat16 h = __float2bfloat16(f);
    rem = f - __bfloat162float(h);
    return *reinterpret_cast<unsigned short*>(&h);
}
__device__ __forceinline__ unsigned short f2bf(float f){
    __nv_bfloat16 h = __float2bfloat16(f);
    return *reinterpret_cast<unsigned short*>(&h);
}

// ---------------- K0 ----------------
__global__ void k_zero(){
    int t = threadIdx.x;
    if (t < FIN){ g_S1[t]=0.f; g_Q1[t]=0.f; }
    if (t < FHID){ g_S2[t]=0.f; g_Q2[t]=0.f; }
    if (t < 2) g_S3[t]=0.f;
}

// ---------------- K1: col stats of adj + fused bf16 hi/lo split ------------------
__global__ __launch_bounds__(256) void k_colstats(const float* __restrict__ adj){
    const int lane = threadIdx.x & 31;
    const int warp = (blockIdx.x*blockDim.x + threadIdx.x) >> 5;
    const int nw   = (gridDim.x*blockDim.x) >> 5;
    uint2* planeH = reinterpret_cast<uint2*>(g_Ah);
    uint2* planeL = reinterpret_cast<uint2*>(g_Al);
    float s0=0.f,s1=0.f,s2=0.f,s3=0.f,q0=0.f,q1=0.f,q2=0.f,q3=0.f;
    for (int r = warp*8; r < MROWS; r += nw*8){
        float4 v[8];
        #pragma unroll
        for (int i = 0; i < 8; i++)
            v[i] = *reinterpret_cast<const float4*>(adj + (size_t)(r+i)*FIN + lane*4);
        #pragma unroll
        for (int i = 0; i < 8; i++){
            s0+=v[i].x; q0+=v[i].x*v[i].x;
            s1+=v[i].y; q1+=v[i].y*v[i].y;
            s2+=v[i].z; q2+=v[i].z*v[i].z;
            s3+=v[i].w; q3+=v[i].w*v[i].w;
            // split to bf16 hi/lo and store (row stride = 32 uint2)
            uint32_t h0 = pack_bf2(v[i].x, v[i].y);
            uint32_t h1 = pack_bf2(v[i].z, v[i].w);
            float rx = v[i].x - __uint_as_float(h0 << 16);
            float ry = v[i].y - __uint_as_float(h0 & 0xFFFF0000u);
            float rz = v[i].z - __uint_as_float(h1 << 16);
            float rw = v[i].w - __uint_as_float(h1 & 0xFFFF0000u);
            uint32_t l0 = pack_bf2(rx, ry);
            uint32_t l1 = pack_bf2(rz, rw);
            planeH[(size_t)(r+i)*32 + lane] = make_uint2(h0, h1);
            planeL[(size_t)(r+i)*32 + lane] = make_uint2(l0, l1);
        }
    }
    __shared__ float bs[FIN], bq[FIN];
    if (threadIdx.x < FIN){ bs[threadIdx.x]=0.f; bq[threadIdx.x]=0.f; }
    __syncthreads();
    atomicAdd(&bs[lane*4+0], s0); atomicAdd(&bs[lane*4+1], s1);
    atomicAdd(&bs[lane*4+2], s2); atomicAdd(&bs[lane*4+3], s3);
    atomicAdd(&bq[lane*4+0], q0); atomicAdd(&bq[lane*4+1], q1);
    atomicAdd(&bq[lane*4+2], q2); atomicAdd(&bq[lane*4+3], q3);
    __syncthreads();
    if (threadIdx.x < FIN){
        atomicAdd(&g_S1[threadIdx.x], bs[threadIdx.x]);
        atomicAdd(&g_Q1[threadIdx.x], bq[threadIdx.x]);
    }
}

// ---------------- K2: fold BN1 into W -> bf16 hi/lo images [n][k] ----------------
__global__ void k_fold1(const float* __restrict__ W,
                        const float* __restrict__ gamma1,
                        const float* __restrict__ beta1){
    __shared__ float s1s[FIN], b1s[FIN];
    int t = threadIdx.x;
    if (t < FIN){
        float mu  = g_S1[t] * (1.f/(float)MROWS);
        float var = g_Q1[t] * (1.f/(float)MROWS) - mu*mu;
        float sc  = gamma1[t] * rsqrtf(var + EPSV);
        s1s[t] = sc;
        b1s[t] = beta1[t] - mu*sc;
    }
    __syncthreads();
    for (int i = t; i < FIN*FHID; i += blockDim.x){
        int k = i >> 6, n = i & 63;
        float w1 = s1s[k] * W[i];
        float rem;
        unsigned short h = f2bf_hi(w1, rem);
        unsigned short l = f2bf(rem);
        reinterpret_cast<unsigned short*>(g_Bh)[n*BSTRIDE + k] = h;
        reinterpret_cast<unsigned short*>(g_Bl)[n*BSTRIDE + k] = l;
    }
    if (t < FHID){
        float acc = 0.f;
        for (int j = 0; j < FIN; j++) acc += b1s[j] * W[j*FHID + t];
        g_cvec[t] = acc;
    }
}

// ---------------- K3: HMMA GEMM, 256-row CTA, M=32/warp, K-split copy staging ---
#define SOFF_AH 0
#define SOFF_AL 36864
#define SOFF_BH 73728
#define SOFF_BL 91136
#define SMEM_TOT 108544

__global__ void __launch_bounds__(256, 2) k_gemm(){
    extern __shared__ __align__(1024) char smem[];
    const uint32_t sb = smem_u32(smem);
    const int t = threadIdx.x;
    const int w = t >> 5, lane = t & 31;
    const int g  = lane >> 2, tc = lane & 3;
    const int row0 = blockIdx.x * 256;

    __shared__ float cs[FHID], cq[FHID];
    if (t < FHID){ cs[t]=0.f; cq[t]=0.f; }

    // B: flat copy of prebuilt images (1088 uint4 each), once
    {
        const uint4* sh = reinterpret_cast<const uint4*>(g_Bh);
        const uint4* sl = reinterpret_cast<const uint4*>(g_Bl);
        uint4* dh = reinterpret_cast<uint4*>(smem + SOFF_BH);
        uint4* dl = reinterpret_cast<uint4*>(smem + SOFF_BL);
        #pragma unroll
        for (int i = 0; i < 5; i++){
            int idx = t + i*256;
            if (idx < 1088){ dh[idx] = sh[idx]; dl[idx] = sl[idx]; }
        }
    }

    // fragment base addresses: warp w owns rows w*32..w*32+31 (2 m-tiles of 16)
    const uint32_t aBase = sb + SOFF_AH +
        (uint32_t)((w*32 + (lane & 15))*ASTRIDE + 8*(lane >> 4))*2u;
    const uint32_t bBase = sb + SOFF_BH +
        (uint32_t)(((lane & 7) + ((lane & 16) >> 1))*BSTRIDE + (lane & 8))*2u;

    float acc[2][8][4];
    #pragma unroll
    for (int mt = 0; mt < 2; mt++)
        #pragma unroll
        for (int nt = 0; nt < 8; nt++)
            #pragma unroll
            for (int i = 0; i < 4; i++) acc[mt][nt][i] = 0.f;

    #pragma unroll
    for (int ph = 0; ph < 2; ph++){
        if (ph == 1) __syncthreads();   // all warps done reading phase-0 A
        // stage A phase: pure coalesced copy from pre-split planes
        // 8 lanes per row: lanes cover 128B contiguous per row-slice
        {
            #pragma unroll
            for (int i = 0; i < 8; i++){
                int idx = t + i*256;          // 0..2047
                int r   = idx >> 3;           // 0..255
                int gg  = idx & 7;            // 0..7
                size_t gidx = (size_t)(row0 + r)*16 + ph*8 + gg;
                uint4 hv = g_Ah[gidx];
                uint4 lv = g_Al[gidx];
                uint32_t off = (uint32_t)(r*ASTRIDE + gg*8)*2u;
                *reinterpret_cast<uint4*>(smem + SOFF_AH + off) = hv;
                *reinterpret_cast<uint4*>(smem + SOFF_AL + off) = lv;
            }
        }
        __syncthreads();

        #pragma unroll
        for (int ksl = 0; ksl < 4; ksl++){
            const uint32_t kA = (uint32_t)(ksl*32);            // 16 bf16 = 32B
            const uint32_t kB = (uint32_t)((ph*4 + ksl)*32);
            uint32_t ah0[4], al0[4], ah1[4], al1[4];
            ldm_x4(ah0, aBase + kA);
            ldm_x4(al0, aBase + kA + (SOFF_AL - SOFF_AH));
            ldm_x4(ah1, aBase + kA + (uint32_t)(16*ASTRIDE*2));
            ldm_x4(al1, aBase + kA + (uint32_t)(16*ASTRIDE*2) + (SOFF_AL - SOFF_AH));
            #pragma unroll
            for (int p = 0; p < 4; p++){
                const uint32_t bo = bBase + kB + (uint32_t)(p*16*BSTRIDE*2);
                uint32_t bh[4], bl[4];
                ldm_x4(bh, bo);
                ldm_x4(bl, bo + (SOFF_BL - SOFF_BH));
                // mt-interleaved: RAW distance 4
                mma_bf16(acc[0][2*p],   ah0, bh);
                mma_bf16(acc[1][2*p],   ah1, bh);
                mma_bf16(acc[0][2*p+1], ah0, bh+2);
                mma_bf16(acc[1][2*p+1], ah1, bh+2);
                mma_bf16(acc[0][2*p],   ah0, bl);
                mma_bf16(acc[1][2*p],   ah1, bl);
                mma_bf16(acc[0][2*p+1], ah0, bl+2);
                mma_bf16(acc[1][2*p+1], ah1, bl+2);
                mma_bf16(acc[0][2*p],   al0, bh);
                mma_bf16(acc[1][2*p],   al1, bh);
                mma_bf16(acc[0][2*p+1], al0, bh+2);
                mma_bf16(acc[1][2*p+1], al1, bh+2);
            }
        }
    }

    // epilogue: per n-tile — add cvec, write y (4 rows/thread), one reduce
    #pragma unroll
    for (int nt = 0; nt < 8; nt++){
        const int c0 = nt*8 + 2*tc;
        const float cv0 = __ldg(&g_cvec[c0]);
        const float cv1 = __ldg(&g_cvec[c0+1]);
        float s0 = 0.f, q0 = 0.f, s1 = 0.f, q1 = 0.f;
        #pragma unroll
        for (int mt = 0; mt < 2; mt++){
            const int r0 = row0 + w*32 + mt*16 + g;
            const int r1 = r0 + 8;
            float v00 = acc[mt][nt][0] + cv0;
            float v01 = acc[mt][nt][1] + cv1;
            float v10 = acc[mt][nt][2] + cv0;
            float v11 = acc[mt][nt][3] + cv1;
            *reinterpret_cast<float2*>(&g_ybuf[(size_t)r0*FHID + c0]) = make_float2(v00, v01);
            *reinterpret_cast<float2*>(&g_ybuf[(size_t)r1*FHID + c0]) = make_float2(v10, v11);
            s0 += v00 + v10;  q0 += v00*v00 + v10*v10;
            s1 += v01 + v11;  q1 += v01*v01 + v11*v11;
        }
        #pragma unroll
        for (int o = 4; o <= 16; o <<= 1){
            s0 += __shfl_xor_sync(0xffffffffu, s0, o);
            q0 += __shfl_xor_sync(0xffffffffu, q0, o);
            s1 += __shfl_xor_sync(0xffffffffu, s1, o);
            q1 += __shfl_xor_sync(0xffffffffu, q1, o);
        }
        if (lane < 4){
            atomicAdd(&cs[c0  ], s0);
            atomicAdd(&cq[c0  ], q0);
            atomicAdd(&cs[c0+1], s1);
            atomicAdd(&cq[c0+1], q1);
        }
    }
    __syncthreads();
    if (t < FHID){
        atomicAdd(&g_S2[t], cs[t]);
        atomicAdd(&g_Q2[t], cq[t]);
    }
}

// ---------------- K4 ----------------
__global__ void k_fold2(const float* __restrict__ gamma2, const float* __restrict__ beta2){
    int t = threadIdx.x;
    if (t < FHID){
        float mu  = g_S2[t] * (1.f/(float)MROWS);
        float var = g_Q2[t] * (1.f/(float)MROWS) - mu*mu;
        float sc  = gamma2[t] * rsqrtf(var + EPSV);
        g_p[t] = sc;
        g_q[t] = beta2[t] - mu*sc;
    }
}

// ---------------- K5: z pass ----------------
__global__ __launch_bounds__(256) void k_zpass(const float* __restrict__ avec){
    const int t    = threadIdx.x;
    const int lane = t & 31;
    const int g    = lane & 7;
    float pc[8], qc[8], ac[8];
    #pragma unroll
    for (int i = 0; i < 4; i++){
        pc[i]   = g_p[g*4+i];      qc[i]   = g_q[g*4+i];      ac[i]   = avec[g*4+i];
        pc[4+i] = g_p[32+g*4+i];   qc[4+i] = g_q[32+g*4+i];   ac[4+i] = avec[32+g*4+i];
    }
    const int warp = (blockIdx.x*blockDim.x + t) >> 5;
    const int nw   = (gridDim.x*blockDim.x) >> 5;
    float zs = 0.f, zq = 0.f;
    for (int base = warp*8; base < MROWS; base += nw*8){
        #pragma unroll
        for (int h = 0; h < 2; h++){
            int row = base + h*4 + (lane >> 3);
            const float4 v0 = *reinterpret_cast<const float4*>(&g_ybuf[(size_t)row*FHID + g*4]);
            const float4 v1 = *reinterpret_cast<const float4*>(&g_ybuf[(size_t)row*FHID + 32 + g*4]);
            float z = 0.f;
            z += leakyf(v0.x*pc[0]+qc[0])*ac[0];
            z += leakyf(v0.y*pc[1]+qc[1])*ac[1];
            z += leakyf(v0.z*pc[2]+qc[2])*ac[2];
            z += leakyf(v0.w*pc[3]+qc[3])*ac[3];
            z += leakyf(v1.x*pc[4]+qc[4])*ac[4];
            z += leakyf(v1.y*pc[5]+qc[5])*ac[5];
            z += leakyf(v1.z*pc[6]+qc[6])*ac[6];
            z += leakyf(v1.w*pc[7]+qc[7])*ac[7];
            z += __shfl_xor_sync(0xffffffffu, z, 1);
            z += __shfl_xor_sync(0xffffffffu, z, 2);
            z += __shfl_xor_sync(0xffffffffu, z, 4);
            if (g == 0){
                g_zbuf[row] = z;
                zs += z; zq += z*z;
            }
        }
    }
    #pragma unroll
    for (int o = 16; o > 0; o >>= 1){
        zs += __shfl_xor_sync(0xffffffffu, zs, o);
        zq += __shfl_xor_sync(0xffffffffu, zq, o);
    }
    if (lane == 0){
        atomicAdd(&g_S3[0], zs);
        atomicAdd(&g_S3[1], zq);
    }
}

// ---------------- K6 ----------------
__global__ void k_fold3(const float* __restrict__ gamma3, const float* __restrict__ beta3){
    float mu  = g_S3[0] * (1.f/(float)MROWS);
    float var = g_S3[1] * (1.f/(float)MROWS) - mu*mu;
    float sc  = gamma3[0] * rsqrtf(var + EPSV);
    g_s3b3[0] = sc;
    g_s3b3[1] = beta3[0] - mu*sc;
}

// ---------------- K7: masked row softmax ----------------
__global__ __launch_bounds__(256) void k_softmax(const float* __restrict__ adj_mean,
                                                 float* __restrict__ out){
    const int row = blockIdx.x;
    const int t   = threadIdx.x;
    const int lane = t & 31, wid = t >> 5;
    const float s3 = g_s3b3[0], b3 = g_s3b3[1];

    const float4 zv = *reinterpret_cast<const float4*>(&g_zbuf[(size_t)row*NROWS + t*4]);
    const float4 mv = *reinterpret_cast<const float4*>(&adj_mean[(size_t)row*NROWS + t*4]);
    float v[4];
    {
        float zz[4] = {zv.x, zv.y, zv.z, zv.w};
        float mm[4] = {mv.x, mv.y, mv.z, mv.w};
        #pragma unroll
        for (int i = 0; i < 4; i++){
            float e = leakyf(zz[i]*s3 + b3);
            v[i] = (mm[i] > 0.f) ? e : NEGV;
        }
    }
    __shared__ float sred[8];
    float mx = fmaxf(fmaxf(v[0],v[1]), fmaxf(v[2],v[3]));
    #pragma unroll
    for (int o = 16; o > 0; o >>= 1) mx = fmaxf(mx, __shfl_xor_sync(0xffffffffu, mx, o));
    if (lane == 0) sred[wid] = mx;
    __syncthreads();
    if (t < 32){
        float m2 = (t < 8) ? sred[t] : -3.4e38f;
        #pragma unroll
        for (int o = 4; o > 0; o >>= 1) m2 = fmaxf(m2, __shfl_xor_sync(0xffffffffu, m2, o));
        if (t == 0) sred[0] = m2;
    }
    __syncthreads();
    mx = sred[0];
    __syncthreads();
    float e[4];
    #pragma unroll
    for (int i = 0; i < 4; i++) e[i] = __expf(v[i] - mx);
    float se = e[0]+e[1]+e[2]+e[3];
    #pragma unroll
    for (int o = 16; o > 0; o >>= 1) se += __shfl_xor_sync(0xffffffffu, se, o);
    if (lane == 0) sred[wid] = se;
    __syncthreads();
    if (t < 32){
        float s2 = (t < 8) ? sred[t] : 0.f;
        #pragma unroll
        for (int o = 4; o > 0; o >>= 1) s2 += __shfl_xor_sync(0xffffffffu, s2, o);
        if (t == 0) sred[0] = s2;
    }
    __syncthreads();
    const float inv = 1.f / sred[0];
    float4 ov = make_float4(e[0]*inv, e[1]*inv, e[2]*inv, e[3]*inv);
    *reinterpret_cast<float4*>(&out[(size_t)row*NROWS + t*4]) = ov;
}

// ---------------- launch ----------------
extern "C" void kernel_launch(void* const* d_in, const int* in_sizes, int n_in,
                              void* d_out, int out_size){
    const float* adj      = (const float*)d_in[0];
    const float* adj_mean = (const float*)d_in[1];
    const float* W        = (const float*)d_in[2];
    const float* a        = (const float*)d_in[3];
    const float* gamma1   = (const float*)d_in[4];
    const float* beta1    = (const float*)d_in[5];
    const float* gamma2   = (const float*)d_in[6];
    const float* beta2    = (const float*)d_in[7];
    const float* gamma3   = (const float*)d_in[8];
    const float* beta3    = (const float*)d_in[9];
    float* out = (float*)d_out;

    cudaFuncSetAttribute(k_gemm, cudaFuncAttributeMaxDynamicSharedMemorySize, SMEM_TOT);

    k_zero    <<<1, 128>>>();
    k_colstats<<<4096, 256>>>(adj);
    k_fold1   <<<1, 256>>>(W, gamma1, beta1);
    k_gemm    <<<MROWS/256, 256, SMEM_TOT>>>();
    k_fold2   <<<1, 64>>>(gamma2, beta2);
    k_zpass   <<<2048, 256>>>(a);
    k_fold3   <<<1, 1>>>(gamma3, beta3);
    k_softmax <<<NROWS, 256>>>(adj_mean, out);
}